// round 7
// baseline (speedup 1.0000x reference)
#include <cuda_runtime.h>
#include <cstdint>

// Problem constants (fixed shapes for this problem instance)
#define BB      4
#define NFULL   65536
#define NSMALL  32768
#define KK      32768
#define FF      256
#define CAP     16      // max copy-events per target vertex (Poisson(0.5) -> max ~8)

// Scratch (device globals; zero-initialized at module load).
// Invariant at entry of every kernel_launch call: d_cnt == 0, d_inv == 0.
// k_gather restores this invariant on every call (lane 0 per row).
__device__ int  d_cnt  [BB * NFULL];           // events targeting vertex v
__device__ int2 d_slots[BB * NFULL * CAP];     // {.x = time s, .y = source vertex f}
__device__ int  d_inv  [BB * NFULL];           // vertex -> (row in images)+1, or 0
__device__ int  d_src  [BB * NFULL];           // final source row per output vertex (-1 => zero)

// First BB*NSMALL threads: build inverse mask map. Next BB*KK: bucket copy events.
__global__ void k_build(const int* __restrict__ mask_idx, const int* __restrict__ order) {
    int i = blockIdx.x * blockDim.x + threadIdx.x;
    if (i < BB * NSMALL) {
        int b = i / NSMALL, p = i % NSMALL;
        int v = __ldg(&mask_idx[i]);               // sorted unique -> no conflicts
        d_inv[b * NFULL + v] = p + 1;              // +1 so that 0 == "not masked"
    } else {
        int j = i - BB * NSMALL;
        if (j < BB * KK) {
            int b = j / KK, k = j % KK;
            int f = __ldg(&order[b * 2 * KK + k]);        // order[b,0,k]
            int t = __ldg(&order[b * 2 * KK + KK + k]);   // order[b,1,k]
            int s = KK - 1 - k;                    // execution time: k=KK-1 runs first (s=0)
            int idx = b * NFULL + t;
            int slot = atomicAdd(&d_cnt[idx], 1);
            if (slot < CAP) d_slots[idx * CAP + slot] = make_int2(s, f);
        }
    }
}

// Per output vertex: chase provenance backward through copy events.
// Each hop moves to a strictly earlier execution time -> guaranteed termination.
__global__ void k_resolve() {
    int i = blockIdx.x * blockDim.x + threadIdx.x;
    if (i >= BB * NFULL) return;
    int base = (i / NFULL) * NFULL;
    int v = i - base;
    int s = 0x7fffffff;
    for (;;) {
        int idx = base + v;
        int c = d_cnt[idx];
        if (c > CAP) c = CAP;
        int bs = -1, bf = 0;
        #pragma unroll 4
        for (int j = 0; j < c; j++) {
            int2 e = d_slots[idx * CAP + j];
            if (e.x < s && e.x > bs) { bs = e.x; bf = e.y; }
        }
        if (bs < 0) break;       // no earlier write to v: v holds its initial value
        v = bf; s = bs;
    }
    d_src[i] = d_inv[base + v] - 1;   // -1 => masked-out (zero row)
}

// 16 threads per row, 2 rows per thread, 4 float4 per (thread,row):
// 8 independent LDG.128 in flight per thread. Per load instruction the warp
// covers 2 rows x contiguous 256B segments (identical footprint to the
// measured-best layout); only per-thread MLP and thread count change.
// Block of 256 threads covers 32 rows: group g (=tid>>4) handles rows
// blk*32+g and blk*32+g+16. Lane 0 of each group resets d_cnt/d_inv.
__global__ void k_gather(const float4* __restrict__ img, float4* __restrict__ out) {
    int lane = threadIdx.x & 15;
    int grp  = threadIdx.x >> 4;                      // 0..15
    int rA   = blockIdx.x * 32 + grp;                 // rows in [0, BB*NFULL)
    int rB   = rA + 16;
    int srcA = d_src[rA];
    int srcB = d_src[rB];
    int bA   = rA >> 16;                              // NFULL = 65536
    int bB   = rB >> 16;

    if (lane == 0) {
        d_cnt[rA] = 0; d_inv[rA] = 0;                 // restore clean state
        d_cnt[rB] = 0; d_inv[rB] = 0;
    }

    float4 a0 = make_float4(0.f, 0.f, 0.f, 0.f);
    float4 a1 = a0, a2 = a0, a3 = a0;
    float4 b0 = a0, b1 = a0, b2 = a0, b3 = a0;
    if (srcA >= 0) {
        const float4* s = img + (size_t)(bA * NSMALL + srcA) * (FF / 4) + lane;
        a0 = s[0]; a1 = s[16]; a2 = s[32]; a3 = s[48];
    }
    if (srcB >= 0) {
        const float4* s = img + (size_t)(bB * NSMALL + srcB) * (FF / 4) + lane;
        b0 = s[0]; b1 = s[16]; b2 = s[32]; b3 = s[48];
    }
    float4* oA = out + (size_t)rA * (FF / 4) + lane;
    float4* oB = out + (size_t)rB * (FF / 4) + lane;
    oA[0] = a0; oA[16] = a1; oA[32] = a2; oA[48] = a3;
    oB[0] = b0; oB[16] = b1; oB[32] = b2; oB[48] = b3;
}

extern "C" void kernel_launch(void* const* d_in, const int* in_sizes, int n_in,
                              void* d_out, int out_size) {
    const float* images   = (const float*)d_in[0];
    const int*   mask_idx = (const int*)  d_in[1];
    const int*   order    = (const int*)  d_in[2];
    // d_in[3] = n_full (constant 65536, unused)

    k_build  <<<(BB * NSMALL + BB * KK + 255) / 256, 256>>>(mask_idx, order);
    k_resolve<<<(BB * NFULL + 255) / 256, 256>>>();
    k_gather <<<BB * NFULL / 32, 256>>>((const float4*)images, (float4*)d_out);
}

// round 8
// speedup vs baseline: 1.0237x; 1.0237x over previous
#include <cuda_runtime.h>
#include <cstdint>

// Problem constants (fixed shapes for this problem instance)
#define BB      4
#define NFULL   65536
#define NSMALL  32768
#define KK      32768
#define FF      256
#define CAP     16      // max copy-events per target vertex (Poisson(0.5) -> max ~8)

// Scratch (device globals; zero-initialized at module load).
// k_clear (first launch of every call) establishes d_cnt==0, d_inv==0, so the
// persistent state may be left dirty at the end of a call.
__device__ int  d_cnt  [BB * NFULL];           // events targeting vertex v
__device__ int2 d_slots[BB * NFULL * CAP];     // {.x = time s, .y = source vertex f}
__device__ int  d_inv  [BB * NFULL];           // vertex -> (row in images)+1, or 0

__global__ void k_clear() {
    int i = blockIdx.x * blockDim.x + threadIdx.x;   // over BB*NFULL/4
    if (i < BB * NFULL / 4) {
        ((int4*)d_cnt)[i] = make_int4(0, 0, 0, 0);
        ((int4*)d_inv)[i] = make_int4(0, 0, 0, 0);
    }
}

// First BB*NSMALL threads: build inverse mask map. Next BB*KK: bucket copy events.
__global__ void k_build(const int* __restrict__ mask_idx, const int* __restrict__ order) {
    int i = blockIdx.x * blockDim.x + threadIdx.x;
    if (i < BB * NSMALL) {
        int b = i / NSMALL, p = i % NSMALL;
        int v = __ldg(&mask_idx[i]);               // sorted unique -> no conflicts
        d_inv[b * NFULL + v] = p + 1;              // +1 so that 0 == "not masked"
    } else {
        int j = i - BB * NSMALL;
        if (j < BB * KK) {
            int b = j / KK, k = j % KK;
            int f = __ldg(&order[b * 2 * KK + k]);        // order[b,0,k]
            int t = __ldg(&order[b * 2 * KK + KK + k]);   // order[b,1,k]
            int s = KK - 1 - k;                    // execution time: k=KK-1 runs first (s=0)
            int idx = b * NFULL + t;
            int slot = atomicAdd(&d_cnt[idx], 1);
            if (slot < CAP) d_slots[idx * CAP + slot] = make_int2(s, f);
        }
    }
}

// Fused resolve + gather.
// 16 threads per row, 4 float4 per thread (4 independent LDG.128 in flight);
// thread t of a group handles float4 indices {t, t+16, t+32, t+48}: each batch
// of 16 threads covers a contiguous 256B segment -> fully coalesced (the
// measured-best layout). Before loading, the group chases its row's provenance
// chain inline (uniform within the group -> chain loads broadcast).
__global__ void k_gather(const float4* __restrict__ img, float4* __restrict__ out) {
    int lane = threadIdx.x & 15;
    int ri   = blockIdx.x * 16 + (threadIdx.x >> 4);  // row index in [0, BB*NFULL)
    int base = ri & ~(NFULL - 1);                     // b * NFULL
    int b    = ri >> 16;                              // NFULL = 65536

    // Resolve provenance: walk backward through copy events.
    // Each hop moves to a strictly earlier execution time -> terminates.
    int v = ri - base;
    int s = 0x7fffffff;
    for (;;) {
        int idx = base + v;
        int c = d_cnt[idx];
        if (c > CAP) c = CAP;
        int bs = -1, bf = 0;
        #pragma unroll 4
        for (int j = 0; j < c; j++) {
            int2 e = d_slots[idx * CAP + j];
            if (e.x < s && e.x > bs) { bs = e.x; bf = e.y; }
        }
        if (bs < 0) break;       // no earlier write to v: v holds its initial value
        v = bf; s = bs;
    }
    int src = d_inv[base + v] - 1;                    // -1 => masked-out (zero row)

    float4 v0 = make_float4(0.f, 0.f, 0.f, 0.f);
    float4 v1 = v0, v2 = v0, v3 = v0;
    if (src >= 0) {
        const float4* sp = img + (size_t)(b * NSMALL + src) * (FF / 4) + lane;
        v0 = sp[0]; v1 = sp[16]; v2 = sp[32]; v3 = sp[48];
    }
    float4* o = out + (size_t)ri * (FF / 4) + lane;
    o[0]  = v0;
    o[16] = v1;
    o[32] = v2;
    o[48] = v3;
}

extern "C" void kernel_launch(void* const* d_in, const int* in_sizes, int n_in,
                              void* d_out, int out_size) {
    const float* images   = (const float*)d_in[0];
    const int*   mask_idx = (const int*)  d_in[1];
    const int*   order    = (const int*)  d_in[2];
    // d_in[3] = n_full (constant 65536, unused)

    k_clear <<<(BB * NFULL / 4 + 255) / 256, 256>>>();
    k_build <<<(BB * NSMALL + BB * KK + 255) / 256, 256>>>(mask_idx, order);
    k_gather<<<BB * NFULL / 16, 256>>>((const float4*)images, (float4*)d_out);
}